// round 14
// baseline (speedup 1.0000x reference)
#include <cuda_runtime.h>

// Max-unpool 2x2 stride 2, NHWC — two-pass direction-polarized version.
//
// Pass 1 (read-heavy):  read x (268MB), write packed 2-bit argmax codes (4MB).
// Pass 2 (write-heavy): read idx (4MB, L2-hot) + pooled (67MB), write out (268MB).
//
// Same total DRAM traffic as the single-pass kernel (~555MB) but each pass is
// nearly unidirectional, avoiding DRAM read/write turnaround in the mixed
// stream that capped the single-pass version at 6.6 TB/s.
//
//   i    = ((n*64+hp)*64 + wp)*64 + c4          (pooled float4 index)
//   base = ((n*128+2hp)*128 + 2wp)*64 + c4      (x/out float4 index)
//        = 4*i - 2*(i & 4095) - (i & 63)

static constexpr int C4_   = 64;            // float4 per channel row
static constexpr int ROW4_ = 128 * C4_;     // x row stride in float4 (8192)
static constexpr int TOTAL4 = 16 * 64 * 64 * C4_;  // 4,194,304 = 16384*256

static constexpr int THREADS_ = 256;
static constexpr int BLOCKS_  = TOTAL4 / THREADS_;  // exact, no tail

// 2-bit argmax code per (window, channel); 4 channels packed per byte.
__device__ unsigned char g_idx[TOTAL4];

__global__ __launch_bounds__(THREADS_)
void unpool_pass1(const float4* __restrict__ x)
{
    int i = blockIdx.x * THREADS_ + threadIdx.x;
    int base = (i << 2) - ((i & 4095) << 1) - (i & 63);

    float4 v00 = __ldcs(x + base);
    float4 v01 = __ldcs(x + base + C4_);
    float4 v10 = __ldcs(x + base + ROW4_);
    float4 v11 = __ldcs(x + base + ROW4_ + C4_);

    float a0[4] = {v00.x, v00.y, v00.z, v00.w};
    float a1[4] = {v01.x, v01.y, v01.z, v01.w};
    float a2[4] = {v10.x, v10.y, v10.z, v10.w};
    float a3[4] = {v11.x, v11.y, v11.z, v11.w};

    unsigned code = 0;
    #pragma unroll
    for (int l = 0; l < 4; ++l) {
        float best = a0[l];
        int bi = 0;
        if (a1[l] > best) { best = a1[l]; bi = 1; }
        if (a2[l] > best) { best = a2[l]; bi = 2; }
        if (a3[l] > best) {              bi = 3; }
        code |= (unsigned)bi << (2 * l);
    }
    // Default policy: we WANT idx resident in L2 for pass 2.
    g_idx[i] = (unsigned char)code;
}

__global__ __launch_bounds__(THREADS_)
void unpool_pass2(const float4* __restrict__ pooled,
                  float4* __restrict__ out)
{
    int i = blockIdx.x * THREADS_ + threadIdx.x;
    int base = (i << 2) - ((i & 4095) << 1) - (i & 63);

    unsigned code = g_idx[i];
    float4 pv = __ldcs(pooled + i);
    float p4[4] = {pv.x, pv.y, pv.z, pv.w};

    float o0[4], o1[4], o2[4], o3[4];
    #pragma unroll
    for (int l = 0; l < 4; ++l) {
        int bi = (code >> (2 * l)) & 3;
        float val = fmaxf(p4[l], 0.0f);
        o0[l] = (bi == 0) ? val : 0.0f;
        o1[l] = (bi == 1) ? val : 0.0f;
        o2[l] = (bi == 2) ? val : 0.0f;
        o3[l] = (bi == 3) ? val : 0.0f;
    }

    __stcs(out + base,               make_float4(o0[0], o0[1], o0[2], o0[3]));
    __stcs(out + base + C4_,         make_float4(o1[0], o1[1], o1[2], o1[3]));
    __stcs(out + base + ROW4_,       make_float4(o2[0], o2[1], o2[2], o2[3]));
    __stcs(out + base + ROW4_ + C4_, make_float4(o3[0], o3[1], o3[2], o3[3]));
}

extern "C" void kernel_launch(void* const* d_in, const int* in_sizes, int n_in,
                              void* d_out, int out_size)
{
    const float4* x      = (const float4*)d_in[0];
    const float4* pooled = (const float4*)d_in[1];
    float4* out          = (float4*)d_out;

    unpool_pass1<<<BLOCKS_, THREADS_>>>(x);
    unpool_pass2<<<BLOCKS_, THREADS_>>>(pooled, out);
}

// round 15
// speedup vs baseline: 1.1126x; 1.1126x over previous
#include <cuda_runtime.h>

// Max-unpool 2x2 stride 2, NHWC — FINAL (best measured config, R6/R13).
// x:      [16, 128, 128, 256] f32   (read once)
// pooled: [16,  64,  64, 256] f32   (read once)
// out:    [16, 128, 128, 256] f32   (write once)
//
// HBM-bound at the sustained mixed read/write ceiling: 6.63 TB/s, 83.7% of
// 8 TB/s spec, kernel ~83us. Config: 1 float4 per thread (28 regs, occ ~80%),
// 256-thread blocks, .cs evict-first streaming hints, exact grid (no bounds
// guard), closed-form index map:
//   i    = ((n*64+hp)*64 + wp)*64 + c4          (pooled float4 index)
//   base = ((n*128+2hp)*128 + 2wp)*64 + c4      (x/out float4 index)
//        = 4*i - 2*(i & 4095) - (i & 63)
//
// Probed and rejected across R1-R14:
//  - 2x unroll (48 regs -> occ 50% -> DRAM 76%), persistent grid (36 regs ->
//    occ 66% -> DRAM 77%): any register growth above 28 costs bandwidth.
//  - 512-thread blocks: noise.
//  - pooled L2::evict_last pin: -1% (natural L2 absorption already optimal).
//  - two-pass direction-polarized (idx codes then scatter): write-dominant
//    stream only sustains 5.5 TB/s -> 100.8us total. Mixed stream wins.

static constexpr int C4_   = 64;            // float4 per channel row
static constexpr int ROW4_ = 128 * C4_;     // x row stride in float4 (8192)
static constexpr int TOTAL4 = 16 * 64 * 64 * C4_;  // 4,194,304 = 16384*256

static constexpr int THREADS_ = 256;
static constexpr int BLOCKS_  = TOTAL4 / THREADS_;  // exact, no tail

__global__ __launch_bounds__(THREADS_)
void unpool_kernel(const float4* __restrict__ x,
                   const float4* __restrict__ pooled,
                   float4* __restrict__ out)
{
    int i = blockIdx.x * THREADS_ + threadIdx.x;

    // base index into x/out at the top-left of this window's 2x2 block
    int base = (i << 2) - ((i & 4095) << 1) - (i & 63);

    float4 v00 = __ldcs(x + base);
    float4 v01 = __ldcs(x + base + C4_);
    float4 v10 = __ldcs(x + base + ROW4_);
    float4 v11 = __ldcs(x + base + ROW4_ + C4_);
    float4 pv  = __ldcs(pooled + i);

    float a0[4] = {v00.x, v00.y, v00.z, v00.w};
    float a1[4] = {v01.x, v01.y, v01.z, v01.w};
    float a2[4] = {v10.x, v10.y, v10.z, v10.w};
    float a3[4] = {v11.x, v11.y, v11.z, v11.w};
    float p4[4] = {pv.x, pv.y, pv.z, pv.w};

    float o0[4], o1[4], o2[4], o3[4];

    #pragma unroll
    for (int l = 0; l < 4; ++l) {
        float best = a0[l];
        int bi = 0;
        if (a1[l] > best) { best = a1[l]; bi = 1; }
        if (a2[l] > best) { best = a2[l]; bi = 2; }
        if (a3[l] > best) {              bi = 3; }
        float val = fmaxf(p4[l], 0.0f);
        o0[l] = (bi == 0) ? val : 0.0f;
        o1[l] = (bi == 1) ? val : 0.0f;
        o2[l] = (bi == 2) ? val : 0.0f;
        o3[l] = (bi == 3) ? val : 0.0f;
    }

    __stcs(out + base,               make_float4(o0[0], o0[1], o0[2], o0[3]));
    __stcs(out + base + C4_,         make_float4(o1[0], o1[1], o1[2], o1[3]));
    __stcs(out + base + ROW4_,       make_float4(o2[0], o2[1], o2[2], o2[3]));
    __stcs(out + base + ROW4_ + C4_, make_float4(o3[0], o3[1], o3[2], o3[3]));
}

extern "C" void kernel_launch(void* const* d_in, const int* in_sizes, int n_in,
                              void* d_out, int out_size)
{
    const float4* x      = (const float4*)d_in[0];
    const float4* pooled = (const float4*)d_in[1];
    float4* out          = (float4*)d_out;

    unpool_kernel<<<BLOCKS_, THREADS_>>>(x, pooled, out);
}